// round 5
// baseline (speedup 1.0000x reference)
#include <cuda_runtime.h>

namespace {
constexpr int T_  = 1024;
constexpr int S_  = 64;
constexpr int D_  = 256;
constexpr int TP_ = 8;
constexpr int C_  = 65;   // 2*H*N_K + 1
}

// Runtime flag: 1 if loc/rand inputs are int64 (we then read the low 32-bit word).
__device__ int g_is64;
// Scratch: raw eu (dot * rsqrt(|nei|^2)) per (t, s).
__device__ float g_eu[T_ * S_];

__global__ void detect_is64(const int* __restrict__ w) {
    int lane = threadIdx.x;
    bool ok = true;
    #pragma unroll
    for (int i = 0; i < 8; i++) {
        int idx = lane + 32 * i;
        int lo = w[2 * idx];
        int hi = w[2 * idx + 1];
        ok = ok && (hi == (lo >> 31));
    }
    unsigned m = __ballot_sync(0xffffffffu, ok);
    if (lane == 0) g_is64 = (m == 0xffffffffu) ? 1 : 0;
}

__device__ __forceinline__ unsigned pack_sgnabs(int v) {
    unsigned a = (unsigned)(v < 0 ? -v : v);
    return a | (v < 0 ? 0x80000000u : 0u);
}

// ---------------------------------------------------------------------------
// Kernel A: pure streaming dot products. No smem, no barriers.
// ---------------------------------------------------------------------------
__global__ __launch_bounds__(256) void eu_kernel(
    const float* __restrict__ sta_emb,
    const float* __restrict__ nei_emb)
{
    const int t    = blockIdx.x;
    const int tid  = threadIdx.x;
    const int lane = tid & 31;
    const int warp = tid >> 5;
    const int q    = lane & 7;

    const float4* sg4 = (const float4*)(sta_emb + (size_t)t * D_);
    #pragma unroll
    for (int it = 0; it < 2; it++) {
        int row = warp * 8 + it * 4 + (lane >> 3);
        const float4* nr = (const float4*)(nei_emb + ((size_t)t * S_ + row) * D_);
        float dot = 0.f, nn = 0.f;
        #pragma unroll
        for (int j = 0; j < 8; j++) {
            float4 bb = nr[q + 8 * j];
            float4 a  = sg4[q + 8 * j];
            dot = fmaf(a.x, bb.x, dot); dot = fmaf(a.y, bb.y, dot);
            dot = fmaf(a.z, bb.z, dot); dot = fmaf(a.w, bb.w, dot);
            nn  = fmaf(bb.x, bb.x, nn); nn  = fmaf(bb.y, bb.y, nn);
            nn  = fmaf(bb.z, bb.z, nn); nn  = fmaf(bb.w, bb.w, nn);
        }
        #pragma unroll
        for (int o = 1; o < 8; o <<= 1) {
            dot += __shfl_xor_sync(0xffffffffu, dot, o);
            nn  += __shfl_xor_sync(0xffffffffu, nn,  o);
        }
        if (q == 0) g_eu[t * S_ + row] = dot * rsqrtf(nn);
    }
}

// ---------------------------------------------------------------------------
// Kernel B: everything else (ALU-bound, tiny memory traffic).
// ---------------------------------------------------------------------------
__global__ __launch_bounds__(256, 4) void crit_rest(
    const int*   __restrict__ sta_loc,
    const int*   __restrict__ nei_loc,
    const int*   __restrict__ rand_numbers,
    const float* __restrict__ sta_emb,
    const float* __restrict__ mask,
    const float* __restrict__ rand_vals,
    const float* __restrict__ t_rand,
    float*       __restrict__ out)
{
    __shared__ float    s_mask[S_];
    __shared__ float    s_cs[S_][TP_];
    __shared__ unsigned s_neiT[TP_][68];   // transposed, padded: (sign<<31)|abs
    __shared__ float    s_PT[TP_][68];     // sqrt(|eu|*mask) * B[s][p], transposed, padded
    __shared__ float    s_swc[68];         // sqrt(|eu|*mask)/128
    __shared__ unsigned s_cnc[C_][TP_];    // packed (sign<<31)|abs
    __shared__ float    s_loss[C_][TP_];   // unnormalized by lth (argmin-invariant)
    __shared__ float    s_red[8];
    __shared__ float    s_l32[2];
    __shared__ float    s_invlth;
    __shared__ float    s_rv[TP_];
    __shared__ float    s_rl[TP_];

    const int t    = blockIdx.x;
    const int tid  = threadIdx.x;
    const int lane = tid & 31;
    const int warp = tid >> 5;
    const int p    = tid & 7;
    const int str  = g_is64 ? 2 : 1;

    // ---------------- Head: small LDGs ----------------
    float sv  = sta_emb[(size_t)t * D_ + tid];
    int   nb0 = nei_loc[((size_t)t * (S_*TP_) + tid) * str];
    int   nb1 = nei_loc[((size_t)t * (S_*TP_) + 256 + tid) * str];
    int   rn  = rand_numbers[((size_t)t * 256 + tid) * str];
    int   sl  = sta_loc[((size_t)t * TP_ + p) * str];
    float eu_raw = 0.f;
    if (tid < S_) {
        s_mask[tid] = mask[(size_t)t * S_ + tid];
        eu_raw      = g_eu[t * S_ + tid];
    }
    float tr = 0.f;
    if (tid < TP_) {
        s_rv[tid] = rand_vals[(size_t)t * TP_ + tid];
        tr        = t_rand[t];
    }

    // ---------------- D: cos_sn + packed nei (no smem deps) ----------------
    {
        int aa = sl < 0 ? -sl : sl;
        #pragma unroll
        for (int it = 0; it < 2; it++) {
            int idx = tid + it * 256;
            int nb  = it ? nb1 : nb0;
            int s = idx >> 3;
            int sg = ((nb ^ sl) < 0);
            int na = nb < 0 ? -nb : nb;
            unsigned x = (unsigned)(na ^ aa) + 1u;
            int v  = __clz((int)x) - 16;
            int iv = sg ? -v : v;
            s_cs[s][p]   = (float)iv * 0.0625f;
            s_neiT[p][s] = (unsigned)na | (nb < 0 ? 0x80000000u : 0u);
        }
    }

    // ---------------- E: cnc packed (no smem deps) ----------------
    {
        int k = tid >> 4, c = tid >> 3;   // c = 2k+j
        int r = sl ^ (1 << k) ^ (rn & ((1 << k) - 1));
        s_cnc[c][p]      = pack_sgnabs(r);
        s_cnc[c + 33][p] = pack_sgnabs(-r);
        if (tid < TP_) s_cnc[32][tid] = pack_sgnabs(sl);
    }

    // |sta|^2 partial reduce
    float ns = sv * sv;
    #pragma unroll
    for (int o = 16; o; o >>= 1) ns += __shfl_xor_sync(0xffffffffu, ns, o);
    if (lane == 0) s_red[warp] = ns;
    __syncthreads();                      // barrier 1

    // ---------------- invlth (warp 2, parallel with C') ----------------
    if (warp == 2) {
        float m = s_mask[lane] + s_mask[lane + 32];
        #pragma unroll
        for (int o = 16; o; o >>= 1) m += __shfl_xor_sync(0xffffffffu, m, o);
        if (lane == 0) s_invlth = 1.0f / (m + 1e-12f);
    }

    // ---------------- C' (warps 0-1): P = sqw*B, swc = sqw/128, loss32 ----------------
    if (tid < S_) {
        float tot = s_red[0] + s_red[1] + s_red[2] + s_red[3]
                  + s_red[4] + s_red[5] + s_red[6] + s_red[7];
        float rns = rsqrtf(tot);
        int s = tid;
        float4 ca = *(const float4*)&s_cs[s][0];
        float4 cb = *(const float4*)&s_cs[s][4];
        float sum = ca.x + ca.y + ca.z + ca.w + cb.x + cb.y + cb.z + cb.w;
        float eu  = eu_raw * rns;
        float w   = fabsf(eu) * s_mask[s];       // lth factored out (argmin-invariant)
        float sqw = sqrtf(w);
        s_swc[s]  = sqw * 0.0078125f;
        float cm  = fmaf(sum, 0.125f, -eu);      // sum/8 - eu
        float csv[8] = {ca.x, ca.y, ca.z, ca.w, cb.x, cb.y, cb.z, cb.w};
        #pragma unroll
        for (int pp = 0; pp < 8; pp++)
            s_PT[pp][s] = sqw * fmaf(csv[pp], -0.125f, cm);
        float t32 = w * cm * cm;
        #pragma unroll
        for (int o = 16; o; o >>= 1) t32 += __shfl_xor_sync(0xffffffffu, t32, o);
        if (lane == 0) s_l32[warp] = t32;
    }
    __syncthreads();                      // barrier 2

    // ---------------- F: loss[c][p] and loss[c+33][p] share the clz chain ----------------
    {
        int c0 = tid >> 3;                 // 0..31
        unsigned ca0   = s_cnc[c0][p];
        unsigned ca1   = s_cnc[c0 + 33][p];
        unsigned sflip = (ca0 ^ ca1) & 0x80000000u;  // 0 iff r==0 (both +0)
        float acc0 = 0.f, acc1 = 0.f;
        const int4*   nt  = (const int4*)&s_neiT[p][0];
        const float4* ptv = (const float4*)&s_PT[p][0];
        const float4* swp = (const float4*)s_swc;
        #pragma unroll
        for (int s4 = 0; s4 < 16; s4++) {
            int4   nv = nt[s4];
            float4 Pv = ptv[s4];
            float4 sw = swp[s4];
            #pragma unroll
            for (int i = 0; i < 4; i++) {
                unsigned ne = (i == 0) ? (unsigned)nv.x : (i == 1) ? (unsigned)nv.y
                            : (i == 2) ? (unsigned)nv.z : (unsigned)nv.w;
                float P   = (i == 0) ? Pv.x : (i == 1) ? Pv.y : (i == 2) ? Pv.z : Pv.w;
                float swv = (i == 0) ? sw.x : (i == 1) ? sw.y : (i == 2) ? sw.z : sw.w;
                unsigned xr = ca0 ^ ne;                       // |c|^|n| bits + sign bit
                unsigned x1 = (xr & 0x1FFFFu) + 1u;
                float uf = (float)(__clz((int)x1) - 16);
                float us0 = __int_as_float(__float_as_int(uf) ^ (xr & 0x80000000u));
                float us1 = __int_as_float(__float_as_int(us0) ^ sflip);
                float h0 = fmaf(us0, swv, P);
                float h1 = fmaf(us1, swv, P);
                acc0 = fmaf(h0, h0, acc0);
                acc1 = fmaf(h1, h1, acc1);
            }
        }
        s_loss[c0][p]      = acc0;
        s_loss[c0 + 33][p] = acc1;
        if (tid < TP_) s_loss[32][tid] = s_l32[0] + s_l32[1];
    }
    __syncthreads();                      // barrier 3

    // ---------------- G: argmin, selection, outputs ----------------
    if (tid < TP_) {
        float best = s_loss[0][tid]; int bc = 0;
        #pragma unroll
        for (int c = 1; c < C_; c++) {
            float v = s_loss[c][tid];
            if (v < best) { best = v; bc = c; }      // first-occurrence argmin
        }
        float rv = s_rv[tid]; int rank = 0;
        #pragma unroll
        for (int q = 0; q < 8; q++) {
            float o = s_rv[q];
            rank += (o < rv) || (o == rv && q < tid); // stable argsort rank
        }
        int selg = (tr < 0.8f);
        int ci = (rank < 4) ? (selg ? bc : 32) : 32;
        unsigned pk = s_cnc[ci][tid];
        int val = (pk & 0x80000000u) ? -(int)(pk & 0x7fffffffu) : (int)pk;
        out[(size_t)t * TP_ + tid] = (float)val;
        s_rl[tid] = s_loss[ci][tid];
        __syncwarp(0x000000ffu);
        if (tid == 0) {
            float rl = 0.f;
            #pragma unroll
            for (int q = 0; q < 8; q++) rl += s_rl[q];
            out[(size_t)T_ * TP_ + t] = rl * 0.125f * s_invlth;
        }
    }
}

extern "C" void kernel_launch(void* const* d_in, const int* in_sizes, int n_in,
                              void* d_out, int out_size) {
    (void)in_sizes; (void)n_in; (void)out_size;
    const int*   sta_loc      = (const int*)  d_in[0];
    const int*   nei_loc      = (const int*)  d_in[1];
    const int*   rand_numbers = (const int*)  d_in[2];
    const float* sta_emb      = (const float*)d_in[3];
    const float* nei_emb      = (const float*)d_in[4];
    const float* mask         = (const float*)d_in[5];
    const float* rand_vals    = (const float*)d_in[6];
    const float* t_rand       = (const float*)d_in[7];
    float* out = (float*)d_out;

    detect_is64<<<1, 32>>>(sta_loc);
    eu_kernel<<<T_, 256>>>(sta_emb, nei_emb);
    crit_rest<<<T_, 256>>>(sta_loc, nei_loc, rand_numbers,
                           sta_emb, mask, rand_vals, t_rand, out);
}

// round 6
// speedup vs baseline: 1.2162x; 1.2162x over previous
#include <cuda_runtime.h>

namespace {
constexpr int T_  = 1024;
constexpr int S_  = 64;
constexpr int D_  = 256;
constexpr int TP_ = 8;
constexpr int C_  = 65;   // 2*H*N_K + 1
}

__device__ __forceinline__ unsigned pack_sgnabs(int v) {
    unsigned a = (unsigned)(v < 0 ? -v : v);
    return a | (v < 0 ? 0x80000000u : 0u);
}

__global__ __launch_bounds__(256, 4) void crit_main(
    const int*   __restrict__ sta_loc,
    const int*   __restrict__ nei_loc,
    const int*   __restrict__ rand_numbers,
    const float* __restrict__ sta_emb,
    const float* __restrict__ nei_emb,
    const float* __restrict__ mask,
    const float* __restrict__ rand_vals,
    const float* __restrict__ t_rand,
    float*       __restrict__ out)
{
    __shared__ float    s_eu[S_];          // raw dot*rsqrt(nn); scaled by rns in C'
    __shared__ float    s_mask[S_];
    __shared__ float    s_cs[S_][TP_];
    __shared__ unsigned s_neiT[TP_][68];   // transposed, padded: (sign<<31)|abs
    __shared__ float    s_PT[TP_][68];     // sqrt(|eu|*mask) * B[s][p], transposed, padded
    __shared__ float    s_swc[68];         // sqrt(|eu|*mask)/128
    __shared__ unsigned s_cnc[C_][TP_];    // packed (sign<<31)|abs
    __shared__ float    s_loss[C_][TP_];   // unnormalized by lth (argmin-invariant)
    __shared__ float    s_red[8];
    __shared__ float    s_l32[2];
    __shared__ float    s_invlth;
    __shared__ float    s_rv[TP_];
    __shared__ float    s_rl[TP_];

    const int t    = blockIdx.x;
    const int tid  = threadIdx.x;
    const int lane = tid & 31;
    const int warp = tid >> 5;
    const int p    = tid & 7;

    // ---------------- Inline int64 detection (per-warp, no barrier) ----------------
    // Reads sta_loc words 0..63 (same data every warp -> consistent result).
    // int64 data: every (lo,hi) pair satisfies hi == lo>>31. Random int32 in
    // (1-N, N): essentially impossible for all 32 pairs to satisfy it.
    int dlo = sta_loc[2 * lane];
    int dhi = sta_loc[2 * lane + 1];

    // str-independent loads issued immediately:
    float sv = sta_emb[(size_t)t * D_ + tid];
    if (tid < S_)  s_mask[tid] = mask[(size_t)t * S_ + tid];
    float tr = 0.f;
    if (tid < TP_) {
        s_rv[tid] = rand_vals[(size_t)t * TP_ + tid];
        tr        = t_rand[t];
    }

    // resolve stride
    unsigned bm = __ballot_sync(0xffffffffu, dhi == (dlo >> 31));
    const int str = (bm == 0xffffffffu) ? 2 : 1;

    // str-dependent small loads (issued before B's FMA work consumes its loads):
    int nb0 = nei_loc[((size_t)t * (S_*TP_) + tid) * str];
    int nb1 = nei_loc[((size_t)t * (S_*TP_) + 256 + tid) * str];
    int rn  = rand_numbers[((size_t)t * 256 + tid) * str];
    int sl  = sta_loc[((size_t)t * TP_ + p) * str];

    // ---------------- B: raw eu[s] = dot/|nei|; sta straight from gmem (L1) ----------------
    {
        int q = lane & 7;
        const float4* sg4 = (const float4*)(sta_emb + (size_t)t * D_);
        #pragma unroll
        for (int it = 0; it < 2; it++) {
            int row = warp * 8 + it * 4 + (lane >> 3);
            const float4* nr = (const float4*)(nei_emb + ((size_t)t * S_ + row) * D_);
            float dot = 0.f, nn = 0.f;
            #pragma unroll
            for (int j = 0; j < 8; j++) {
                float4 bb = nr[q + 8 * j];
                float4 a  = sg4[q + 8 * j];
                dot = fmaf(a.x, bb.x, dot); dot = fmaf(a.y, bb.y, dot);
                dot = fmaf(a.z, bb.z, dot); dot = fmaf(a.w, bb.w, dot);
                nn  = fmaf(bb.x, bb.x, nn); nn  = fmaf(bb.y, bb.y, nn);
                nn  = fmaf(bb.z, bb.z, nn); nn  = fmaf(bb.w, bb.w, nn);
            }
            #pragma unroll
            for (int o = 1; o < 8; o <<= 1) {
                dot += __shfl_xor_sync(0xffffffffu, dot, o);
                nn  += __shfl_xor_sync(0xffffffffu, nn,  o);
            }
            if (q == 0) s_eu[row] = dot * rsqrtf(nn);
        }
    }

    // ---------------- D: cos_sn + packed nei (no smem deps) ----------------
    {
        int aa = sl < 0 ? -sl : sl;
        #pragma unroll
        for (int it = 0; it < 2; it++) {
            int idx = tid + it * 256;
            int nb  = it ? nb1 : nb0;
            int s = idx >> 3;
            int sg = ((nb ^ sl) < 0);
            int na = nb < 0 ? -nb : nb;
            unsigned x = (unsigned)(na ^ aa) + 1u;
            int v  = __clz((int)x) - 16;
            int iv = sg ? -v : v;
            s_cs[s][p]   = (float)iv * 0.0625f;
            s_neiT[p][s] = (unsigned)na | (nb < 0 ? 0x80000000u : 0u);
        }
    }

    // ---------------- E: cnc packed (no smem deps) ----------------
    {
        int k = tid >> 4, c = tid >> 3;   // c = 2k+j
        int r = sl ^ (1 << k) ^ (rn & ((1 << k) - 1));
        s_cnc[c][p]      = pack_sgnabs(r);
        s_cnc[c + 33][p] = pack_sgnabs(-r);
        if (tid < TP_) s_cnc[32][tid] = pack_sgnabs(sl);
    }

    // |sta|^2 partial reduce
    float ns = sv * sv;
    #pragma unroll
    for (int o = 16; o; o >>= 1) ns += __shfl_xor_sync(0xffffffffu, ns, o);
    if (lane == 0) s_red[warp] = ns;
    __syncthreads();                      // barrier 1

    // ---------------- invlth (warp 2, parallel with C') ----------------
    if (warp == 2) {
        float m = s_mask[lane] + s_mask[lane + 32];
        #pragma unroll
        for (int o = 16; o; o >>= 1) m += __shfl_xor_sync(0xffffffffu, m, o);
        if (lane == 0) s_invlth = 1.0f / (m + 1e-12f);
    }

    // ---------------- C' (warps 0-1): P = sqw*B, swc = sqw/128, loss32 ----------------
    if (tid < S_) {
        float tot = s_red[0] + s_red[1] + s_red[2] + s_red[3]
                  + s_red[4] + s_red[5] + s_red[6] + s_red[7];
        float rns = rsqrtf(tot);
        int s = tid;
        float4 ca = *(const float4*)&s_cs[s][0];
        float4 cb = *(const float4*)&s_cs[s][4];
        float sum = ca.x + ca.y + ca.z + ca.w + cb.x + cb.y + cb.z + cb.w;
        float eu  = s_eu[s] * rns;
        float w   = fabsf(eu) * s_mask[s];       // lth factored out (argmin-invariant)
        float sqw = sqrtf(w);
        s_swc[s]  = sqw * 0.0078125f;
        float cm  = fmaf(sum, 0.125f, -eu);      // sum/8 - eu
        float csv[8] = {ca.x, ca.y, ca.z, ca.w, cb.x, cb.y, cb.z, cb.w};
        #pragma unroll
        for (int pp = 0; pp < 8; pp++)
            s_PT[pp][s] = sqw * fmaf(csv[pp], -0.125f, cm);
        float t32 = w * cm * cm;
        #pragma unroll
        for (int o = 16; o; o >>= 1) t32 += __shfl_xor_sync(0xffffffffu, t32, o);
        if (lane == 0) s_l32[warp] = t32;
    }
    __syncthreads();                      // barrier 2

    // ---------------- F: loss[c][p] and loss[c+33][p] share the clz chain ----------------
    {
        int c0 = tid >> 3;                 // 0..31
        unsigned ca0   = s_cnc[c0][p];
        unsigned ca1   = s_cnc[c0 + 33][p];
        unsigned sflip = (ca0 ^ ca1) & 0x80000000u;  // 0 iff r==0 (both +0)
        float acc0 = 0.f, acc1 = 0.f;
        const int4*   nt  = (const int4*)&s_neiT[p][0];
        const float4* ptv = (const float4*)&s_PT[p][0];
        const float4* swp = (const float4*)s_swc;
        #pragma unroll
        for (int s4 = 0; s4 < 16; s4++) {
            int4   nv = nt[s4];
            float4 Pv = ptv[s4];
            float4 sw = swp[s4];
            #pragma unroll
            for (int i = 0; i < 4; i++) {
                unsigned ne = (i == 0) ? (unsigned)nv.x : (i == 1) ? (unsigned)nv.y
                            : (i == 2) ? (unsigned)nv.z : (unsigned)nv.w;
                float P   = (i == 0) ? Pv.x : (i == 1) ? Pv.y : (i == 2) ? Pv.z : Pv.w;
                float swv = (i == 0) ? sw.x : (i == 1) ? sw.y : (i == 2) ? sw.z : sw.w;
                unsigned xr = ca0 ^ ne;                       // |c|^|n| bits + sign bit
                unsigned x1 = (xr & 0x1FFFFu) + 1u;
                float uf = (float)(__clz((int)x1) - 16);
                float us0 = __int_as_float(__float_as_int(uf) ^ (xr & 0x80000000u));
                float us1 = __int_as_float(__float_as_int(us0) ^ sflip);
                float h0 = fmaf(us0, swv, P);
                float h1 = fmaf(us1, swv, P);
                acc0 = fmaf(h0, h0, acc0);
                acc1 = fmaf(h1, h1, acc1);
            }
        }
        s_loss[c0][p]      = acc0;
        s_loss[c0 + 33][p] = acc1;
        if (tid < TP_) s_loss[32][tid] = s_l32[0] + s_l32[1];
    }
    __syncthreads();                      // barrier 3

    // ---------------- G: argmin, selection, outputs ----------------
    if (tid < TP_) {
        float best = s_loss[0][tid]; int bc = 0;
        #pragma unroll
        for (int c = 1; c < C_; c++) {
            float v = s_loss[c][tid];
            if (v < best) { best = v; bc = c; }      // first-occurrence argmin
        }
        float rv = s_rv[tid]; int rank = 0;
        #pragma unroll
        for (int q = 0; q < 8; q++) {
            float o = s_rv[q];
            rank += (o < rv) || (o == rv && q < tid); // stable argsort rank
        }
        int selg = (tr < 0.8f);
        int ci = (rank < 4) ? (selg ? bc : 32) : 32;
        unsigned pk = s_cnc[ci][tid];
        int val = (pk & 0x80000000u) ? -(int)(pk & 0x7fffffffu) : (int)pk;
        out[(size_t)t * TP_ + tid] = (float)val;
        s_rl[tid] = s_loss[ci][tid];
        __syncwarp(0x000000ffu);
        if (tid == 0) {
            float rl = 0.f;
            #pragma unroll
            for (int q = 0; q < 8; q++) rl += s_rl[q];
            out[(size_t)T_ * TP_ + t] = rl * 0.125f * s_invlth;
        }
    }
}

extern "C" void kernel_launch(void* const* d_in, const int* in_sizes, int n_in,
                              void* d_out, int out_size) {
    (void)in_sizes; (void)n_in; (void)out_size;
    const int*   sta_loc      = (const int*)  d_in[0];
    const int*   nei_loc      = (const int*)  d_in[1];
    const int*   rand_numbers = (const int*)  d_in[2];
    const float* sta_emb      = (const float*)d_in[3];
    const float* nei_emb      = (const float*)d_in[4];
    const float* mask         = (const float*)d_in[5];
    const float* rand_vals    = (const float*)d_in[6];
    const float* t_rand       = (const float*)d_in[7];
    float* out = (float*)d_out;

    crit_main<<<T_, 256>>>(sta_loc, nei_loc, rand_numbers,
                           sta_emb, nei_emb, mask, rand_vals, t_rand, out);
}